// round 4
// baseline (speedup 1.0000x reference)
#include <cuda_runtime.h>

// CRF NLL, B=256, S=256, T=128 (126 tags + START/STOP)
// Scaled-probability forward recursion, E = exp(transitions) in registers.
//   s_j = sum_i w_i * E[i][j]
//   w'_j = s_j * exp(f_j) / (128 * w0)      (w0 = w[0], read by all threads)
//   N   += log(w0) + log(128)               (p_j = N + log w_j at the end)
// No per-step serial work on the barrier-publisher path; LPT batch scheduling.

#define B_   256
#define S_   256
#define T_   128
#define LOG128 4.852030263919617f

__device__ float g_partial[B_];
__device__ int   g_order[B_];

#define FMA2(d, a, b, c) \
    asm("fma.rn.f32x2 %0, %1, %2, %3;" : "=l"(d) : "l"(a), "l"(b), "l"(c))
#define ADD2(d, a, b) \
    asm("add.rn.f32x2 %0, %1, %2;" : "=l"(d) : "l"(a), "l"(b))
#define PACK2(d, lo, hi) \
    asm("mov.b64 %0, {%1, %2};" : "=l"(d) : "f"(lo), "f"(hi))
#define UNPACK2(lo, hi, s) \
    asm("mov.b64 {%0, %1}, %2;" : "=f"(lo), "=f"(hi) : "l"(s))

__device__ __forceinline__ float warpMax(float x) {
#pragma unroll
    for (int o = 16; o; o >>= 1) x = fmaxf(x, __shfl_xor_sync(0xffffffffu, x, o));
    return x;
}
__device__ __forceinline__ float warpSum(float x) {
#pragma unroll
    for (int o = 16; o; o >>= 1) x += __shfl_xor_sync(0xffffffffu, x, o);
    return x;
}

// ---- prep: lengths + bitonic sort (descending) -> g_order (LPT schedule) ----
__global__ void prep_kernel(const int* __restrict__ mask) {
    __shared__ unsigned key[B_];
    const int b = threadIdx.x;
    const int4* m4 = (const int4*)(mask + b * S_);
    int len = 0;
#pragma unroll
    for (int i = 0; i < S_ / 4; ++i) {
        int4 v = m4[i];
        len += v.x + v.y + v.z + v.w;
    }
    key[b] = ((unsigned)len << 16) | (unsigned)b;
    __syncthreads();
    for (int k = 2; k <= B_; k <<= 1) {
        for (int j = k >> 1; j; j >>= 1) {
            int ixj = b ^ j;
            if (ixj > b) {
                unsigned a = key[b], c = key[ixj];
                bool up = (b & k) == 0;            // descending sort
                if (up ? (a < c) : (a > c)) { key[b] = c; key[ixj] = a; }
            }
            __syncthreads();
        }
    }
    g_order[b] = (int)(key[b] & 0xFFFFu);
}

__global__ void __launch_bounds__(128, 2) crf_kernel(
    const float* __restrict__ feats,       // [B, S, T]
    const float* __restrict__ trans,       // [T, T]
    const void*  __restrict__ tags_raw,    // [B, S] int64 OR int32 (auto-detect)
    const int*   __restrict__ mask)        // [B, S] prefix mask
{
    __shared__ __align__(16) float wb[2][128];
    __shared__ float red[8];

    const int b    = g_order[blockIdx.x];
    const int tid  = threadIdx.x;
    const int lane = tid & 31;
    const int wid  = tid >> 5;
    const int START = T_ - 2, STOP = T_ - 1;

    // ---- detect tags dtype (int64 from jax-x64, or silently-demoted int32) ----
    int is64;
    {
        const int* t32 = (const int*)tags_raw;
        int bad = 0;
#pragma unroll
        for (int k = 0; k < 16; ++k) bad |= t32[2 * k + 1];
        is64 = (bad == 0);
    }

    // ---- E column j=tid in registers: e[m] = {exp(tr[2m][j]), exp(tr[2m+1][j])} ----
    unsigned long long e[T_ / 2];
    {
        const float* tc = trans + tid;
#pragma unroll
        for (int m = 0; m < T_ / 2; ++m) {
            float a = __expf(tc[(2 * m) * T_]);
            float c = __expf(tc[(2 * m + 1) * T_]);
            PACK2(e[m], a, c);
        }
    }
    const float tstart = trans[START * T_ + tid];   // trans[START][j]
    const float tstop  = trans[tid * T_ + STOP];    // trans[j][STOP]

    const float* fb = feats + (size_t)b * (S_ * T_);
    const int*   mb = mask + b * S_;

    // ---- init: p0 = feat0 + trans[START];  w0 = exp(p0 - p0[0]);  N = p0[0] ----
    float p0 = fb[tid] + tstart;
    if (tid == 0) red[0] = p0;
    __syncthreads();
    const float m0 = red[0];
    float wreg = __expf(p0 - m0);
    wb[0][tid] = wreg;
    float N = m0;                            // per-thread, identical across block

    const float* fp = fb + T_ + tid;
    float fnext = *fp;
    int   mnext = mb[1];
    int   buf = 0, len = S_;

    for (int t = 1; t < S_; ++t) {
        __syncthreads();                     // publishes wb[buf] (+ reuse guard)
        if (!mnext) { len = t; break; }
        float f = fnext;
        if (t + 1 < S_) { fp += T_; fnext = *fp; mnext = mb[t + 1]; }

        const ulonglong2* wv = (const ulonglong2*)wb[buf];

        // normalizer from broadcast w0 (off the barrier critical path)
        float w0 = wb[buf][0];
        float scale = __frcp_rn(w0) * 0.0078125f;     // 1/(128*w0)
        float ef = __expf(f) * scale;
        N += __logf(w0) + LOG128;

        unsigned long long a0 = 0ull, a1 = 0ull, a2 = 0ull, a3 = 0ull;
#pragma unroll
        for (int k = 0; k < 32; k += 2) {
            ulonglong2 wA = wv[k];
            ulonglong2 wB = wv[k + 1];
            FMA2(a0, wA.x, e[2 * k],     a0);
            FMA2(a1, wA.y, e[2 * k + 1], a1);
            FMA2(a2, wB.x, e[2 * k + 2], a2);
            FMA2(a3, wB.y, e[2 * k + 3], a3);
        }
        ADD2(a0, a0, a2);
        ADD2(a1, a1, a3);
        ADD2(a0, a0, a1);
        float s0, s1;
        UNPACK2(s0, s1, a0);
        wreg = (s0 + s1) * ef;

        buf ^= 1;
        wb[buf][tid] = wreg;                 // symmetric: no thread-0 extra work
    }

    // ---- final: forward_b = logsumexp_i(p_i + trans[i, STOP]),  p = N + log w ----
    float p = N + __logf(wreg);              // -inf for START (w=0): fine under max
    float m = warpMax(p);
    if (lane == 0) red[wid] = m;
    __syncthreads();
    m = fmaxf(fmaxf(red[0], red[1]), fmaxf(red[2], red[3]));
    float term = wreg * __expf(N - m + tstop);    // exp(p - m + tstop), 0-safe
    float ssum = warpSum(term);
    if (lane == 0) red[4 + wid] = ssum;
    __syncthreads();
    float fwd = m + __logf(red[4] + red[5] + red[6] + red[7]);

    // ---- gold path score ----
    const long long* t64 = (const long long*)tags_raw;
    const int*       t32 = (const int*)tags_raw;
    const size_t tbase = (size_t)b * S_;
    float g = 0.f;
    for (int t = tid; t < S_; t += 128) {
        if (mb[t]) {
            int tag  = is64 ? (int)t64[tbase + t] : t32[tbase + t];
            int prev = (t == 0) ? START
                                : (is64 ? (int)t64[tbase + t - 1] : t32[tbase + t - 1]);
            g += fb[t * T_ + tag] + trans[prev * T_ + tag];
        }
    }
    g = warpSum(g);
    __syncthreads();                          // order vs red[4..7] reads above
    if (lane == 0) red[wid] = g;
    __syncthreads();

    if (tid == 0) {
        int end_id = is64 ? (int)t64[tbase + len - 1] : t32[tbase + len - 1];
        float gold = red[0] + red[1] + red[2] + red[3]
                   + trans[end_id * T_ + STOP];
        g_partial[b] = fwd - gold;
    }
}

// Deterministic tree reduction of the 256 per-batch partials.
__global__ void reduce_kernel(float* __restrict__ out) {
    __shared__ float sb[8];
    int tid = threadIdx.x;
    float x = g_partial[tid];
    x = warpSum(x);
    if ((tid & 31) == 0) sb[tid >> 5] = x;
    __syncthreads();
    if (tid == 0) {
        float s = 0.f;
#pragma unroll
        for (int i = 0; i < 8; ++i) s += sb[i];
        out[0] = s;
    }
}

extern "C" void kernel_launch(void* const* d_in, const int* in_sizes, int n_in,
                              void* d_out, int out_size) {
    const float* feats = (const float*)d_in[0];
    const float* trans = (const float*)d_in[1];
    const void*  tags  = d_in[2];
    const int*   mask  = (const int*)d_in[3];

    prep_kernel<<<1, 256>>>(mask);
    crf_kernel<<<B_, 128>>>(feats, trans, tags, mask);
    reduce_kernel<<<1, 256>>>((float*)d_out);
}